// round 1
// baseline (speedup 1.0000x reference)
#include <cuda_runtime.h>
#include <math.h>

#define Bv 4
#define Tv 4096
#define Cv 512
#define Rv (Bv*Tv)            // 16384 rows
#define Fv (4*Cv)             // 2048
#define GUARDE (2048*Cv)      // guard rows (zero-init) for shifted scan operand

// ---------------- static device scratch (zero-initialized) ----------------
__device__ float g_h[Rv*Cv];
__device__ float g_qA[GUARDE + Rv*Cv];
__device__ float g_qB[GUARDE + Rv*Cv];
__device__ float g_v[Rv*Cv];
__device__ float g_z[Rv*Cv];
__device__ float g_fc[Rv*Fv];
__device__ float g_X [2*Cv*Cv];
__device__ float g_X2[2*Cv*Cv];
__device__ float g_Y [2*Cv*Cv];
__device__ float g_Mm[2*Cv*Cv];
__device__ float g_part[2*Cv];
__device__ float g_rn[2];

// ---------------- GEMM ----------------
// C[M,N] = f(alpha * A?B + beta*add + diag*I)
// AM=0: A is K-major, A[m*K+k]      AM=1: A is M-major, A[k*M+m] (i.e. uses A^T)
// BMO=0: B is K-major, B[n*K+k] (C=A.B^T)   BMO=1: B is N-major, B[k*N+n] (C=A.B)
struct Epi {
    float alpha;
    const float* add;
    float beta;
    float diag;
    int gelu;
    long strideAdd;
};

template<int BM,int BN,int BK,int TM,int TN,int AM,int BMO>
__global__ __launch_bounds__((BM/TM)*(BN/TN))
void gemm_k(const float* __restrict__ A, const float* __restrict__ Bp,
            float* __restrict__ C, int M, int N, int K,
            long sA, long sB, long sC, Epi e)
{
    constexpr int NT = (BM/TM)*(BN/TN);
    __shared__ __align__(16) float Sa[BK][BM+4];
    __shared__ __align__(16) float Sb[BK][BN+4];
    const int tid = threadIdx.x;
    const int bz  = blockIdx.z;
    A  += (long)bz * sA;
    Bp += (long)bz * sB;
    C  += (long)bz * sC;
    const float* Ad = e.add ? (e.add + (long)bz * e.strideAdd) : (const float*)0;
    const int m0 = blockIdx.y * BM;
    const int n0 = blockIdx.x * BN;
    const int tx = tid % (BN/TN);
    const int ty = tid / (BN/TN);

    float acc[TM][TN];
#pragma unroll
    for (int i=0;i<TM;i++)
#pragma unroll
        for (int j=0;j<TN;j++) acc[i][j]=0.f;

    for (int k0=0; k0<K; k0+=BK) {
        // load A tile -> Sa[k][m]
        {
            constexpr int NV = BM*BK/4;
#pragma unroll
            for (int t=0; t<NV/NT; t++) {
                int vv = tid + t*NT;
                if (AM==0) {
                    int m  = vv/(BK/4);
                    int kk = (vv%(BK/4))*4;
                    float4 f = *(const float4*)(A + (long)(m0+m)*K + (k0+kk));
                    Sa[kk+0][m]=f.x; Sa[kk+1][m]=f.y; Sa[kk+2][m]=f.z; Sa[kk+3][m]=f.w;
                } else {
                    int kk = vv/(BM/4);
                    int mm = (vv%(BM/4))*4;
                    *(float4*)&Sa[kk][mm] = *(const float4*)(A + (long)(k0+kk)*M + (m0+mm));
                }
            }
        }
        // load B tile -> Sb[k][n]
        {
            constexpr int NV = BN*BK/4;
#pragma unroll
            for (int t=0; t<NV/NT; t++) {
                int vv = tid + t*NT;
                if (BMO==0) {
                    int n  = vv/(BK/4);
                    int kk = (vv%(BK/4))*4;
                    float4 f = *(const float4*)(Bp + (long)(n0+n)*K + (k0+kk));
                    Sb[kk+0][n]=f.x; Sb[kk+1][n]=f.y; Sb[kk+2][n]=f.z; Sb[kk+3][n]=f.w;
                } else {
                    int kk = vv/(BN/4);
                    int nn = (vv%(BN/4))*4;
                    *(float4*)&Sb[kk][nn] = *(const float4*)(Bp + (long)(k0+kk)*N + (n0+nn));
                }
            }
        }
        __syncthreads();
#pragma unroll
        for (int k=0;k<BK;k++) {
            float ra[TM], rb[TN];
#pragma unroll
            for (int i=0;i<TM;i+=4) {
                float4 t4 = *(const float4*)&Sa[k][ty*TM+i];
                ra[i]=t4.x; ra[i+1]=t4.y; ra[i+2]=t4.z; ra[i+3]=t4.w;
            }
#pragma unroll
            for (int j=0;j<TN;j+=4) {
                float4 t4 = *(const float4*)&Sb[k][tx*TN+j];
                rb[j]=t4.x; rb[j+1]=t4.y; rb[j+2]=t4.z; rb[j+3]=t4.w;
            }
#pragma unroll
            for (int i=0;i<TM;i++)
#pragma unroll
                for (int j=0;j<TN;j++)
                    acc[i][j] = fmaf(ra[i], rb[j], acc[i][j]);
        }
        __syncthreads();
    }

#pragma unroll
    for (int i=0;i<TM;i++) {
        int gm = m0 + ty*TM + i;
#pragma unroll
        for (int j=0;j<TN;j++) {
            int gn = n0 + tx*TN + j;
            float v = e.alpha * acc[i][j];
            if (Ad) v += e.beta * Ad[(long)gm*N + gn];
            if (e.diag != 0.f && gm==gn) v += e.diag;
            if (e.gelu) v = 0.5f*v*(1.f + erff(v*0.70710678118654752f));
            C[(long)gm*N + gn] = v;
        }
    }
}

// ---------------- elementwise / reduction kernels ----------------
__global__ void ln_kernel(const float* __restrict__ x, const float* __restrict__ w,
                          float* __restrict__ o)
{
    const int r = blockIdx.x, tid = threadIdx.x; // 128 threads, C=512 => 1 float4/thr
    float4 f = ((const float4*)(x + (long)r*Cv))[tid];
    float s = f.x+f.y+f.z+f.w;
    float q = f.x*f.x+f.y*f.y+f.z*f.z+f.w*f.w;
    __shared__ float shs[4], shq[4];
#pragma unroll
    for (int off=16; off>0; off>>=1) {
        s += __shfl_down_sync(0xffffffffu, s, off);
        q += __shfl_down_sync(0xffffffffu, q, off);
    }
    if ((tid&31)==0) { shs[tid>>5]=s; shq[tid>>5]=q; }
    __syncthreads();
    float S = shs[0]+shs[1]+shs[2]+shs[3];
    float Q = shq[0]+shq[1]+shq[2]+shq[3];
    float mean = S*(1.f/Cv);
    float var  = Q*(1.f/Cv) - mean*mean;
    float inv  = rsqrtf(var + 1e-5f);
    float4 wf = ((const float4*)w)[tid];
    float4 r4;
    r4.x = (f.x-mean)*inv*wf.x;
    r4.y = (f.y-mean)*inv*wf.y;
    r4.z = (f.z-mean)*inv*wf.z;
    r4.w = (f.w-mean)*inv*wf.w;
    ((float4*)(o + (long)r*Cv))[tid] = r4;
}

__global__ void pscan_combine(const float* __restrict__ z, const float* __restrict__ qold,
                              float* __restrict__ qnew, int d)
{
    const int r = blockIdx.x, tid = threadIdx.x;
    const int t = r & (Tv-1);
    if (t < d) {
        ((float4*)(qnew + (long)r*Cv))[tid] = ((const float4*)(qold + (long)r*Cv))[tid];
        return;
    }
    float4 f = ((const float4*)(z + (long)r*Cv))[tid];
    float q = f.x*f.x+f.y*f.y+f.z*f.z+f.w*f.w;
    __shared__ float shq[4];
#pragma unroll
    for (int off=16; off>0; off>>=1) q += __shfl_down_sync(0xffffffffu, q, off);
    if ((tid&31)==0) shq[tid>>5]=q;
    __syncthreads();
    float Q = shq[0]+shq[1]+shq[2]+shq[3];
    float sc = rsqrtf(Q*(1.f/Cv) + 1e-6f);
    float4 r4; r4.x=f.x*sc; r4.y=f.y*sc; r4.z=f.z*sc; r4.w=f.w*sc;
    ((float4*)(qnew + (long)r*Cv))[tid] = r4;
}

__global__ void mul_k(const float* __restrict__ a, const float* __restrict__ b,
                      float* __restrict__ o)
{
    long i = (long)blockIdx.x*blockDim.x + threadIdx.x;  // R*C/4 float4s exactly
    float4 fa = ((const float4*)a)[i];
    float4 fb = ((const float4*)b)[i];
    float4 r4; r4.x=fa.x*fb.x; r4.y=fa.y*fb.y; r4.z=fa.z*fb.z; r4.w=fa.w*fb.w;
    ((float4*)o)[i] = r4;
}

__global__ void frob1(const float* __restrict__ W1, const float* __restrict__ W2,
                      float* __restrict__ part)
{
    const int row = blockIdx.x, mat = blockIdx.y, tid = threadIdx.x;
    const float* W = mat ? W2 : W1;
    float4 f = ((const float4*)(W + (long)row*Cv))[tid];
    float q = f.x*f.x+f.y*f.y+f.z*f.z+f.w*f.w;
    __shared__ float shq[4];
#pragma unroll
    for (int off=16; off>0; off>>=1) q += __shfl_down_sync(0xffffffffu, q, off);
    if ((tid&31)==0) shq[tid>>5]=q;
    __syncthreads();
    if (tid==0) part[mat*Cv + row] = shq[0]+shq[1]+shq[2]+shq[3];
}

__global__ void frob2(const float* __restrict__ part, float* __restrict__ rn)
{
    const int mat = blockIdx.x, tid = threadIdx.x;  // 256 threads
    __shared__ float sh[256];
    sh[tid] = part[mat*Cv + tid] + part[mat*Cv + tid + 256];
    __syncthreads();
    for (int off=128; off>0; off>>=1) {
        if (tid<off) sh[tid] += sh[tid+off];
        __syncthreads();
    }
    if (tid==0) rn[mat] = rsqrtf(sh[0]);
}

__global__ void polar_scale(const float* __restrict__ W1, const float* __restrict__ W2,
                            const float* __restrict__ rn, float* __restrict__ X)
{
    int idx = blockIdx.x*blockDim.x + threadIdx.x;   // 2*512*512 total
    int mat = idx >> 18;
    float w = mat ? W2[idx - Cv*Cv] : W1[idx];
    X[idx] = w * rn[mat];
}

// ---------------- host ----------------
static inline Epi epi_none() { Epi e; e.alpha=1.f; e.add=0; e.beta=0.f; e.diag=0.f; e.gelu=0; e.strideAdd=0; return e; }

extern "C" void kernel_launch(void* const* d_in, const int* in_sizes, int n_in,
                              void* d_out, int out_size)
{
    const float* x   = (const float*)d_in[0];
    const float* ln1 = (const float*)d_in[1];
    const float* Wq  = (const float*)d_in[2];
    const float* Wv  = (const float*)d_in[3];
    const float* Wo  = (const float*)d_in[4];
    // d_in[5] = identity : mathematically unused (its rows are discarded by the where-mask)
    const float* Wp1 = (const float*)d_in[6];
    const float* Wp2 = (const float*)d_in[7];
    const float* ln2 = (const float*)d_in[8];
    const float* Wfc = (const float*)d_in[9];
    const float* Wpr = (const float*)d_in[10];
    float* out = (float*)d_out;

    float *h,*qA,*qB,*v,*z,*fc,*X,*X2,*Y,*Mm,*part,*rn;
    cudaGetSymbolAddress((void**)&h,  g_h);
    cudaGetSymbolAddress((void**)&qA, g_qA);
    cudaGetSymbolAddress((void**)&qB, g_qB);
    cudaGetSymbolAddress((void**)&v,  g_v);
    cudaGetSymbolAddress((void**)&z,  g_z);
    cudaGetSymbolAddress((void**)&fc, g_fc);
    cudaGetSymbolAddress((void**)&X,  g_X);
    cudaGetSymbolAddress((void**)&X2, g_X2);
    cudaGetSymbolAddress((void**)&Y,  g_Y);
    cudaGetSymbolAddress((void**)&Mm, g_Mm);
    cudaGetSymbolAddress((void**)&part, g_part);
    cudaGetSymbolAddress((void**)&rn,   g_rn);

    float* qAb = qA + GUARDE;
    float* qBb = qB + GUARDE;
    const long S = (long)Cv*Cv;
    Epi e0 = epi_none();

    // ---- polar factors of Wp1, Wp2 via Muon-quintic + Newton-Schulz ----
    frob1<<<dim3(Cv,2),128>>>(Wp1, Wp2, part);
    frob2<<<2,256>>>(part, rn);
    polar_scale<<<(2*Cv*Cv)/256,256>>>(Wp1, Wp2, rn, X);

    float* Xc = X;  float* Xn = X2;
    for (int it=0; it<10; ++it) {   // quintic: X <- X(aI + bY + cY^2), Y = X^T X
        gemm_k<64,64,16,4,4,1,1><<<dim3(8,8,2),256>>>(Xc, Xc, Y, Cv,Cv,Cv, S,S,S, e0);
        Epi em = e0; em.alpha=2.0315f; em.add=Y; em.beta=-4.7750f; em.diag=3.4445f; em.strideAdd=S;
        gemm_k<64,64,16,4,4,0,1><<<dim3(8,8,2),256>>>(Y, Y, Mm, Cv,Cv,Cv, S,S,S, em);
        gemm_k<64,64,16,4,4,0,1><<<dim3(8,8,2),256>>>(Xc, Mm, Xn, Cv,Cv,Cv, S,S,S, e0);
        float* tmp=Xc; Xc=Xn; Xn=tmp;
    }
    for (int it=0; it<8; ++it) {    // Newton-Schulz: X <- 1.5X - 0.5 X (X^T X)
        gemm_k<64,64,16,4,4,1,1><<<dim3(8,8,2),256>>>(Xc, Xc, Y, Cv,Cv,Cv, S,S,S, e0);
        Epi en = e0; en.alpha=-0.5f; en.add=Xc; en.beta=1.5f; en.strideAdd=S;
        gemm_k<64,64,16,4,4,0,1><<<dim3(8,8,2),256>>>(Xc, Y, Xn, Cv,Cv,Cv, S,S,S, en);
        float* tmp=Xc; Xc=Xn; Xn=tmp;
    }
    const float* P1 = Xc;
    const float* P2 = Xc + S;

    // ---- SSM branch ----
    ln_kernel<<<Rv,128>>>(x, ln1, h);
    gemm_k<128,128,16,8,8,0,0><<<dim3(Cv/128, Rv/128, 1),256>>>(h, Wq, qAb, Rv,Cv,Cv, 0,0,0, e0);
    gemm_k<128,128,16,8,8,0,0><<<dim3(Cv/128, Rv/128, 1),256>>>(h, Wv, v,   Rv,Cv,Cv, 0,0,0, e0);

    float* qc = qAb;  float* qn = qBb;
    for (int d=1; d<Tv; d<<=1) {
        // z = qshift @ P1^T  (guard rows are zeros; invalid rows discarded below)
        gemm_k<128,128,16,8,8,0,0><<<dim3(Cv/128, Rv/128, 1),256>>>(qc - (long)d*Cv, P1, z, Rv,Cv,Cv, 0,0,0, e0);
        // z += q @ P2^T
        Epi ea = e0; ea.add=z; ea.beta=1.f;
        gemm_k<128,128,16,8,8,0,0><<<dim3(Cv/128, Rv/128, 1),256>>>(qc, P2, z, Rv,Cv,Cv, 0,0,0, ea);
        pscan_combine<<<Rv,128>>>(z, qc, qn, d);
        float* tmp=qc; qc=qn; qn=tmp;
    }

    // x1 = x + (q*v) @ Wo^T   (into d_out)
    mul_k<<<(Rv*Cv/4)/256,256>>>(qc, v, h);
    Epi er = e0; er.add=x; er.beta=1.f;
    gemm_k<128,128,16,8,8,0,0><<<dim3(Cv/128, Rv/128, 1),256>>>(h, Wo, out, Rv,Cv,Cv, 0,0,0, er);

    // ---- MLP branch ----
    ln_kernel<<<Rv,128>>>(out, ln2, h);
    Epi eg = e0; eg.gelu=1;
    gemm_k<128,128,16,8,8,0,0><<<dim3(Fv/128, Rv/128, 1),256>>>(h, Wfc, fc, Rv,Fv,Cv, 0,0,0, eg);
    Epi er2 = e0; er2.add=out; er2.beta=1.f;
    gemm_k<128,128,16,8,8,0,0><<<dim3(Cv/128, Rv/128, 1),256>>>(fc, Wpr, out, Rv,Cv,Fv, 0,0,0, er2);
}